// round 1
// baseline (speedup 1.0000x reference)
#include <cuda_runtime.h>
#include <cuda_bf16.h>

// Problem constants (fixed by the reference)
#define PB 64
#define PT 512
#define PD 1024
#define TS 16          // T-chunks
#define TT (PT / TS)   // 32 rows per main block

// Scratch (no allocations allowed -> __device__ globals)
__device__ float g_W[PB * PT];   // gathered per-token weights (masked)
__device__ float g_S[PB * PD];   // unnormalized s[b,d]

// ---------------------------------------------------------------------------
// Kernel 1: gather weights, zero scratch + y_hat output region
// grid (PB), block (512)
// ---------------------------------------------------------------------------
__global__ void k_prep(const int* __restrict__ len,
                       const int* __restrict__ word,
                       const float* __restrict__ weights,
                       float* __restrict__ out_yh)
{
    const int b = blockIdx.x;
    const int t = threadIdx.x;
    const int L = len[b];
    g_W[b * PT + t] = (t < L) ? weights[word[b * PT + t]] : 0.0f;

    // zero s scratch and y_hat output (512 threads cover 1024 each, x2)
    g_S[b * PD + t]        = 0.0f;
    g_S[b * PD + t + 512]  = 0.0f;
    out_yh[b * PD + t]       = 0.0f;
    out_yh[b * PD + t + 512] = 0.0f;
}

// ---------------------------------------------------------------------------
// Kernel 2: masked partial sums over a T-chunk, accumulate via atomics.
// grid (2, TS, PB), block (128). Each thread owns one float4 d-column.
// Blocks whose whole t-range is masked exit before any global load.
// ---------------------------------------------------------------------------
__global__ void __launch_bounds__(128)
k_main(const float* __restrict__ vs,
       const int* __restrict__ len,
       float* __restrict__ out_yh)
{
    const int b  = blockIdx.z;
    const int L  = len[b];
    const int t0 = blockIdx.y * TT;
    if (t0 >= L) return;                       // fully masked chunk: no traffic
    const int n  = min(t0 + TT, L) - t0;

    const int d0 = blockIdx.x * 512 + threadIdx.x * 4;

    __shared__ float wsh[TT];
    if (threadIdx.x < TT) wsh[threadIdx.x] = g_W[b * PT + t0 + threadIdx.x];
    __syncthreads();

    const float4* __restrict__ p =
        reinterpret_cast<const float4*>(vs + ((size_t)b * PT + t0) * PD + d0);
    const size_t stride = PD / 4;

    float4 acc  = make_float4(0.f, 0.f, 0.f, 0.f);
    float4 accw = make_float4(0.f, 0.f, 0.f, 0.f);

#pragma unroll 4
    for (int i = 0; i < n; ++i) {
        const float4 v = p[(size_t)i * stride];
        const float  w = wsh[i];
        acc.x  += v.x;      acc.y  += v.y;      acc.z  += v.z;      acc.w  += v.w;
        accw.x += w * v.x;  accw.y += w * v.y;  accw.z += w * v.z;  accw.w += w * v.w;
    }

    float* sp = g_S + (size_t)b * PD + d0;
    atomicAdd(sp + 0, acc.x);
    atomicAdd(sp + 1, acc.y);
    atomicAdd(sp + 2, acc.z);
    atomicAdd(sp + 3, acc.w);

    float* yp = out_yh + (size_t)b * PD + d0;
    atomicAdd(yp + 0, accw.x);
    atomicAdd(yp + 1, accw.y);
    atomicAdd(yp + 2, accw.z);
    atomicAdd(yp + 3, accw.w);
}

// ---------------------------------------------------------------------------
// Kernel 3: per-b L1 norm of s, write y = s * rsqrt(sum|s|).
// grid (PB), block (256); each thread holds one float4 (256*4 = 1024 = D).
// ---------------------------------------------------------------------------
__global__ void k_norm(float* __restrict__ out_y)
{
    const int b   = blockIdx.x;
    const int tid = threadIdx.x;

    const float4 s4 = reinterpret_cast<const float4*>(g_S + (size_t)b * PD)[tid];
    float part = fabsf(s4.x) + fabsf(s4.y) + fabsf(s4.z) + fabsf(s4.w);

#pragma unroll
    for (int o = 16; o > 0; o >>= 1)
        part += __shfl_xor_sync(0xFFFFFFFFu, part, o);

    __shared__ float sm[8];
    if ((tid & 31) == 0) sm[tid >> 5] = part;
    __syncthreads();

    float tot = 0.f;
#pragma unroll
    for (int i = 0; i < 8; ++i) tot += sm[i];

    const float r = rsqrtf(tot);
    float4 y4 = make_float4(s4.x * r, s4.y * r, s4.z * r, s4.w * r);
    reinterpret_cast<float4*>(out_y + (size_t)b * PD)[tid] = y4;
}

// ---------------------------------------------------------------------------
// Entry point
// ---------------------------------------------------------------------------
extern "C" void kernel_launch(void* const* d_in, const int* in_sizes, int n_in,
                              void* d_out, int out_size)
{
    const float* vs      = (const float*)d_in[0];  // [B,T,D] f32
    const int*   len     = (const int*)  d_in[1];  // [B]
    const int*   word    = (const int*)  d_in[2];  // [B,T]
    const float* weights = (const float*)d_in[3];  // [VOCAB]

    float* out    = (float*)d_out;      // y at [0, B*D), y_hat at [B*D, 2*B*D)
    float* out_yh = out + PB * PD;

    k_prep<<<PB, 512>>>(len, word, weights, out_yh);
    k_main<<<dim3(2, TS, PB), 128>>>(vs, len, out_yh);
    k_norm<<<PB, 256>>>(out);
}

// round 3
// speedup vs baseline: 1.1261x; 1.1261x over previous
#include <cuda_runtime.h>
#include <cuda_bf16.h>

// Problem constants (fixed by the reference)
#define PB 64
#define PT 512
#define PD 1024
#define TS 16          // T-chunks
#define TT (PT / TS)   // 32 rows per main block (== warp size)

// Zero-invariant scratch: statically zero-initialized at module load;
// k_norm restores zeros after consuming, so every kernel_launch call
// (correctness run + each graph replay) sees zeros. No prep kernel needed.
__device__ float g_S [PB * PD];   // unnormalized s[b,d]
__device__ float g_YH[PB * PD];   // unnormalized y_hat[b,d]

// ---------------------------------------------------------------------------
// Kernel 1: masked partial sums over a T-chunk, accumulate via atomics.
// grid (2, TS, PB), block (128). Each thread owns one float4 d-column.
// Blocks whose whole t-range is masked exit before any global load.
// Per-token weights are gathered per-warp into lane registers and
// broadcast with __shfl_sync — no smem, no barrier, gather overlaps the
// independent vs streaming loads.
// ---------------------------------------------------------------------------
__global__ void __launch_bounds__(128)
k_main(const float* __restrict__ vs,
       const int* __restrict__ len,
       const int* __restrict__ word,
       const float* __restrict__ weights)
{
    const int b  = blockIdx.z;
    const int L  = __ldg(len + b);
    const int t0 = blockIdx.y * TT;
    if (t0 >= L) return;                       // fully masked chunk: no traffic
    const int n  = min(L - t0, TT);

    // Each warp: lane j holds w_j = weights[word[b, t0+j]] (value unused
    // beyond n; indices always in-bounds since t0+lane < 512).
    const int lane = threadIdx.x & 31;
    const float wlane = weights[word[b * PT + t0 + lane]];

    const int d0 = blockIdx.x * 512 + threadIdx.x * 4;

    const float4* __restrict__ p =
        reinterpret_cast<const float4*>(vs + ((size_t)b * PT + t0) * PD + d0);
    const size_t stride = PD / 4;

    float4 acc  = make_float4(0.f, 0.f, 0.f, 0.f);
    float4 accw = make_float4(0.f, 0.f, 0.f, 0.f);

#pragma unroll 4
    for (int i = 0; i < n; ++i) {
        const float4 v = p[(size_t)i * stride];
        const float  w = __shfl_sync(0xFFFFFFFFu, wlane, i);
        acc.x  += v.x;      acc.y  += v.y;      acc.z  += v.z;      acc.w  += v.w;
        accw.x += w * v.x;  accw.y += w * v.y;  accw.z += w * v.z;  accw.w += w * v.w;
    }

    float* sp = g_S + (size_t)b * PD + d0;
    atomicAdd(sp + 0, acc.x);
    atomicAdd(sp + 1, acc.y);
    atomicAdd(sp + 2, acc.z);
    atomicAdd(sp + 3, acc.w);

    float* yp = g_YH + (size_t)b * PD + d0;
    atomicAdd(yp + 0, accw.x);
    atomicAdd(yp + 1, accw.y);
    atomicAdd(yp + 2, accw.z);
    atomicAdd(yp + 3, accw.w);
}

// ---------------------------------------------------------------------------
// Kernel 2: per-b L1 norm of s, write y = s * rsqrt(sum|s|) and y_hat,
// then restore the zero-invariant on the scratch buffers.
// grid (PB), block (256); each thread holds one float4 (256*4 = 1024 = D).
// ---------------------------------------------------------------------------
__global__ void __launch_bounds__(256)
k_norm(float* __restrict__ out)
{
    const int b   = blockIdx.x;
    const int tid = threadIdx.x;

    float4* sP = reinterpret_cast<float4*>(g_S  + (size_t)b * PD) + tid;
    float4* hP = reinterpret_cast<float4*>(g_YH + (size_t)b * PD) + tid;
    const float4 s4 = *sP;
    const float4 h4 = *hP;

    float part = fabsf(s4.x) + fabsf(s4.y) + fabsf(s4.z) + fabsf(s4.w);

#pragma unroll
    for (int o = 16; o > 0; o >>= 1)
        part += __shfl_xor_sync(0xFFFFFFFFu, part, o);

    __shared__ float sm[8];
    if ((tid & 31) == 0) sm[tid >> 5] = part;
    __syncthreads();

    float tot = 0.f;
#pragma unroll
    for (int i = 0; i < 8; ++i) tot += sm[i];

    const float r = rsqrtf(tot);

    float* out_y  = out;
    float* out_yh = out + PB * PD;
    reinterpret_cast<float4*>(out_y  + (size_t)b * PD)[tid] =
        make_float4(s4.x * r, s4.y * r, s4.z * r, s4.w * r);
    reinterpret_cast<float4*>(out_yh + (size_t)b * PD)[tid] = h4;

    // restore zero-invariant for the next launch/replay
    const float4 z = make_float4(0.f, 0.f, 0.f, 0.f);
    *sP = z;
    *hP = z;
}

// ---------------------------------------------------------------------------
// Entry point
// ---------------------------------------------------------------------------
extern "C" void kernel_launch(void* const* d_in, const int* in_sizes, int n_in,
                              void* d_out, int out_size)
{
    const float* vs      = (const float*)d_in[0];  // [B,T,D] f32
    const int*   len     = (const int*)  d_in[1];  // [B]
    const int*   word    = (const int*)  d_in[2];  // [B,T]
    const float* weights = (const float*)d_in[3];  // [VOCAB]

    float* out = (float*)d_out;  // y at [0, B*D), y_hat at [B*D, 2*B*D)

    k_main<<<dim3(2, TS, PB), 128>>>(vs, len, word, weights);
    k_norm<<<PB, 256>>>(out);
}